// round 4
// baseline (speedup 1.0000x reference)
#include <cuda_runtime.h>
#include <cstdint>

#define D_MODEL 1024
#define SEQ     2048
#define BATCH   2
#define NHEAD   16
#define DK      64
#define MTOT    (BATCH * SEQ)

// Scratch (allocation-free rule)
__device__ float g_Q[BATCH * SEQ * D_MODEL];
__device__ float g_K[BATCH * SEQ * D_MODEL];
__device__ float g_V[BATCH * SEQ * D_MODEL];
__device__ float g_att[BATCH * SEQ * D_MODEL];

// ---------------------------------------------------------------------------
__device__ __forceinline__ uint32_t f2tf(float f) {
    uint32_t u;
    asm("cvt.rna.tf32.f32 %0, %1;" : "=r"(u) : "f"(f));
    return u;
}

__device__ __forceinline__ void mma_tf32(float* d, const uint32_t* a,
                                         const uint32_t* b, const float* c) {
    asm volatile(
        "mma.sync.aligned.m16n8k8.row.col.f32.tf32.tf32.f32 "
        "{%0,%1,%2,%3}, {%4,%5,%6,%7}, {%8,%9}, {%10,%11,%12,%13};\n"
        : "=f"(d[0]), "=f"(d[1]), "=f"(d[2]), "=f"(d[3])
        : "r"(a[0]), "r"(a[1]), "r"(a[2]), "r"(a[3]),
          "r"(b[0]), "r"(b[1]),
          "f"(c[0]), "f"(c[1]), "f"(c[2]), "f"(c[3]));
}

// ---------------------------------------------------------------------------
// TF32 GEMM, 128x128x16 tiles, 8 warps (4m x 2n), warp tile 32x64.
// Fragment-shuffled smem: STS scatters into mma-fragment order so every
// fragment load in the hot loop is a single LDS.128.
//   A: [kk(2)][wr(4)][gid(8) stride36][tig(4)][mt(2)][4 regs]  (conflict-free)
//   B: [k(16) stride132][cperm], cperm = (c&64)+(c&7)*8+((c>>3)&7)
// ---------------------------------------------------------------------------
#define A_BUF 2304   // 2*1152
#define B_BUF 2112   // 16*132

__device__ __forceinline__ void gemm_tf32_body(const float* __restrict__ A,
                                               const float* __restrict__ B,
                                               float* __restrict__ C,
                                               int M, int N, int K,
                                               int bm, int bn) {
    __shared__ uint32_t Asp[2][A_BUF];
    __shared__ uint32_t Bsp[2][B_BUF];

    const int tid = threadIdx.x;
    const int w = tid >> 5, lane = tid & 31;
    const int wr = w >> 1, wc = w & 1;
    const int gid = lane >> 2, tig = lane & 3;

    float acc[2][8][4] = {};
    float4 avr[2], bvr[2];

    const int ar0 = tid >> 2, ac0 = (tid & 3) * 4;   // A rows 0..63
    const int ar1 = 64 + ar0, ac1 = ac0;             // A rows 64..127
    const int br0 = tid >> 5, bc0 = (tid & 31) * 4;  // B rows 0..7
    const int br1 = 8 + br0, bc1 = bc0;              // B rows 8..15

    auto load_regs = [&](int k0) {
        avr[0] = *(const float4*)(A + (size_t)(bm + ar0) * K + k0 + ac0);
        avr[1] = *(const float4*)(A + (size_t)(bm + ar1) * K + k0 + ac1);
        bvr[0] = *(const float4*)(B + (size_t)(k0 + br0) * N + bn + bc0);
        bvr[1] = *(const float4*)(B + (size_t)(k0 + br1) * N + bn + bc1);
    };

    auto sts_A = [&](int buf, int ar, int ac, float4 v) {
        int kk = ac >> 3, khi = (ac >> 2) & 1;
        int wr_ = ar >> 5, mt = (ar >> 4) & 1, rhi = (ar >> 3) & 1, g = ar & 7;
        uint32_t* p = &Asp[buf][kk * 1152 + wr_ * 288 + g * 36 + mt * 4 +
                               rhi + 2 * khi];
        p[0] = f2tf(v.x); p[8] = f2tf(v.y); p[16] = f2tf(v.z); p[24] = f2tf(v.w);
    };
    auto sts_B = [&](int buf, int br, int bc, float4 v) {
        uint32_t* p = &Bsp[buf][br * 132 + (bc & 64) + (bc & 4) * 8 +
                                ((bc >> 3) & 7)];
        p[0] = f2tf(v.x); p[8] = f2tf(v.y); p[16] = f2tf(v.z); p[24] = f2tf(v.w);
    };
    auto store_smem = [&](int buf) {
        sts_A(buf, ar0, ac0, avr[0]);
        sts_A(buf, ar1, ac1, avr[1]);
        sts_B(buf, br0, bc0, bvr[0]);
        sts_B(buf, br1, bc1, bvr[1]);
    };

    load_regs(0);
    store_smem(0);
    __syncthreads();

    int buf = 0;
    for (int k0 = 0; k0 < K; k0 += 16, buf ^= 1) {
        const bool more = (k0 + 16) < K;
        if (more) load_regs(k0 + 16);

#pragma unroll
        for (int kk = 0; kk < 2; kk++) {
            const uint32_t* Ab = &Asp[buf][kk * 1152 + wr * 288 + gid * 36 + tig * 8];
            uint32_t af[2][4];
            *(uint4*)&af[0][0] = *(const uint4*)(Ab);
            *(uint4*)&af[1][0] = *(const uint4*)(Ab + 4);

            const uint32_t* Bb = &Bsp[buf][(kk * 8 + tig) * 132 + wc * 64 + gid * 8];
            uint32_t bx[8], by[8];
            *(uint4*)&bx[0] = *(const uint4*)(Bb);
            *(uint4*)&bx[4] = *(const uint4*)(Bb + 4);
            *(uint4*)&by[0] = *(const uint4*)(Bb + 528);
            *(uint4*)&by[4] = *(const uint4*)(Bb + 532);

#pragma unroll
            for (int mt = 0; mt < 2; mt++)
#pragma unroll
                for (int nt = 0; nt < 8; nt++) {
                    uint32_t bf[2] = {bx[nt], by[nt]};
                    mma_tf32(acc[mt][nt], af[mt], bf, acc[mt][nt]);
                }
        }

        if (more) {
            store_smem(buf ^ 1);
            __syncthreads();
        }
    }

#pragma unroll
    for (int mt = 0; mt < 2; mt++)
#pragma unroll
        for (int nt = 0; nt < 8; nt++) {
            int row = bm + wr * 32 + mt * 16 + gid;
            int col = bn + wc * 64 + nt * 8 + 2 * tig;
            *(float2*)(C + (size_t)row * N + col) =
                make_float2(acc[mt][nt][0], acc[mt][nt][1]);
            *(float2*)(C + (size_t)(row + 8) * N + col) =
                make_float2(acc[mt][nt][2], acc[mt][nt][3]);
        }
}

__global__ __launch_bounds__(256)
void gemm_qkv_kernel(const float* __restrict__ x,
                     const float* __restrict__ Wq,
                     const float* __restrict__ Wk,
                     const float* __restrict__ Wv) {
    const float* W = (blockIdx.z == 0) ? Wq : (blockIdx.z == 1) ? Wk : Wv;
    float* C = (blockIdx.z == 0) ? g_Q : (blockIdx.z == 1) ? g_K : g_V;
    gemm_tf32_body(x, W, C, MTOT, D_MODEL, D_MODEL,
                   blockIdx.y * 128, blockIdx.x * 128);
}

__global__ __launch_bounds__(256)
void gemm_kernel(const float* __restrict__ A, const float* __restrict__ B,
                 float* __restrict__ C, int M, int N, int K) {
    gemm_tf32_body(A, B, C, M, N, K, blockIdx.y * 128, blockIdx.x * 128);
}

// ---------------------------------------------------------------------------
// Flash attention, TF32 mma. CTA = (128 q rows, head, batch), 256 threads.
// Register-staged K/V: gmem loads overlap the mma blocks; 2 barriers/iter.
// 1/sqrt(dk)=0.125 folded into Q conversion (exact, power of two).
// smem: Qs[128][68] (aliased as Ps after Q hoist), Ks[64][68], Vs[64][72].
// ---------------------------------------------------------------------------
#define QS_STRIDE 68
#define VS_STRIDE 72
#define SM_Q 0
#define SM_K (128 * QS_STRIDE)
#define SM_V (SM_K + 64 * QS_STRIDE)
#define ATTN_SMEM_UINTS (SM_V + 64 * VS_STRIDE)
#define ATTN_SMEM_BYTES (ATTN_SMEM_UINTS * 4)

__global__ __launch_bounds__(256)
void attn_kernel(const float* __restrict__ Q, const float* __restrict__ K,
                 const float* __restrict__ V, float* __restrict__ O) {
    extern __shared__ uint32_t sm[];
    uint32_t* Qs = sm + SM_Q;
    uint32_t* Ps = sm + SM_Q;   // aliased: Qs dead after fragment hoist
    uint32_t* Ks = sm + SM_K;
    uint32_t* Vs = sm + SM_V;

    const int qt = blockIdx.x, h = blockIdx.y, b = blockIdx.z;
    const int tid = threadIdx.x;
    const int w = tid >> 5, lane = tid & 31;
    const int gid = lane >> 2, tig = lane & 3;

    const float* Qbase = Q + ((size_t)b * SEQ + qt * 128) * D_MODEL + h * DK;
    const float* Kbase = K + (size_t)b * SEQ * D_MODEL + h * DK;
    const float* Vbase = V + (size_t)b * SEQ * D_MODEL + h * DK;

    // Load + convert Q tile (128 x 64), scale folded in.
#pragma unroll
    for (int i = 0; i < 8; i++) {
        int idx = i * 256 + tid;
        int r = idx >> 4, c = (idx & 15) * 4;
        float4 v = *(const float4*)(Qbase + (size_t)r * D_MODEL + c);
        *(uint4*)&Qs[r * QS_STRIDE + c] =
            make_uint4(f2tf(v.x * 0.125f), f2tf(v.y * 0.125f),
                       f2tf(v.z * 0.125f), f2tf(v.w * 0.125f));
    }
    __syncthreads();

    // Hoist Q fragments; Qs smem dead after this (becomes Ps).
    const int r0 = w * 16 + gid;
    uint32_t qf[8][4];
#pragma unroll
    for (int kc = 0; kc < 8; kc++) {
        qf[kc][0] = Qs[r0 * QS_STRIDE + kc * 8 + tig];
        qf[kc][1] = Qs[(r0 + 8) * QS_STRIDE + kc * 8 + tig];
        qf[kc][2] = Qs[r0 * QS_STRIDE + kc * 8 + tig + 4];
        qf[kc][3] = Qs[(r0 + 8) * QS_STRIDE + kc * 8 + tig + 4];
    }
    __syncthreads();   // all warps done reading Qs before Ps overwrites

    const int ldr = tid >> 4, ldc = (tid & 15) * 4;  // each thread: 4 rows apart

    float o[8][4] = {};
    float m0 = -1e30f, m1 = -1e30f, l0 = 0.f, l1 = 0.f;

    float4 kregs[4], vregs[4];
#pragma unroll
    for (int i = 0; i < 4; i++)
        kregs[i] = *(const float4*)(Kbase + (size_t)(ldr + i * 16) * D_MODEL + ldc);

    for (int kt = 0; kt < SEQ / 64; kt++) {
        // Commit staged K tile; start V load (consumed after next barrier+mma).
#pragma unroll
        for (int i = 0; i < 4; i++) {
            int r = ldr + i * 16;
            *(uint4*)&Ks[r * QS_STRIDE + ldc] =
                make_uint4(f2tf(kregs[i].x), f2tf(kregs[i].y),
                           f2tf(kregs[i].z), f2tf(kregs[i].w));
        }
        const float* vb = Vbase + (size_t)kt * 64 * D_MODEL;
#pragma unroll
        for (int i = 0; i < 4; i++)
            vregs[i] = *(const float4*)(vb + (size_t)(ldr + i * 16) * D_MODEL + ldc);
        __syncthreads();

        // S = Q @ K^T (16 x 64 per warp) — overlaps V gmem load
        float s[8][4] = {};
#pragma unroll
        for (int kc = 0; kc < 8; kc++) {
#pragma unroll
            for (int nt = 0; nt < 8; nt++) {
                uint32_t kf[2];
                int kvp = nt * 8 + gid;
                kf[0] = Ks[kvp * QS_STRIDE + kc * 8 + tig];
                kf[1] = Ks[kvp * QS_STRIDE + kc * 8 + tig + 4];
                mma_tf32(s[nt], qf[kc], kf, s[nt]);
            }
        }

        float mx0 = -1e30f, mx1 = -1e30f;
#pragma unroll
        for (int nt = 0; nt < 8; nt++) {
            mx0 = fmaxf(mx0, fmaxf(s[nt][0], s[nt][1]));
            mx1 = fmaxf(mx1, fmaxf(s[nt][2], s[nt][3]));
        }
        mx0 = fmaxf(mx0, __shfl_xor_sync(0xffffffffu, mx0, 1));
        mx0 = fmaxf(mx0, __shfl_xor_sync(0xffffffffu, mx0, 2));
        mx1 = fmaxf(mx1, __shfl_xor_sync(0xffffffffu, mx1, 1));
        mx1 = fmaxf(mx1, __shfl_xor_sync(0xffffffffu, mx1, 2));

        float nm0 = fmaxf(m0, mx0), nm1 = fmaxf(m1, mx1);
        float corr0 = __expf(m0 - nm0), corr1 = __expf(m1 - nm1);
        m0 = nm0; m1 = nm1;

        float rs0 = 0.f, rs1 = 0.f;
#pragma unroll
        for (int nt = 0; nt < 8; nt++) {
            float p0 = __expf(s[nt][0] - nm0);
            float p1 = __expf(s[nt][1] - nm0);
            float p2 = __expf(s[nt][2] - nm1);
            float p3 = __expf(s[nt][3] - nm1);
            rs0 += p0 + p1;
            rs1 += p2 + p3;
            int col = nt * 8 + 2 * tig;
            *(uint2*)&Ps[r0 * QS_STRIDE + col] = make_uint2(f2tf(p0), f2tf(p1));
            *(uint2*)&Ps[(r0 + 8) * QS_STRIDE + col] = make_uint2(f2tf(p2), f2tf(p3));
        }
        rs0 += __shfl_xor_sync(0xffffffffu, rs0, 1);
        rs0 += __shfl_xor_sync(0xffffffffu, rs0, 2);
        rs1 += __shfl_xor_sync(0xffffffffu, rs1, 1);
        rs1 += __shfl_xor_sync(0xffffffffu, rs1, 2);
        l0 = l0 * corr0 + rs0;
        l1 = l1 * corr1 + rs1;

#pragma unroll
        for (int nt = 0; nt < 8; nt++) {
            o[nt][0] *= corr0; o[nt][1] *= corr0;
            o[nt][2] *= corr1; o[nt][3] *= corr1;
        }
        __syncwarp();  // Ps rows warp-private: order STS -> LDS

        // Commit staged V tile; start next K load (consumed after barrier+PV).
#pragma unroll
        for (int i = 0; i < 4; i++) {
            int r = ldr + i * 16;
            *(uint4*)&Vs[r * VS_STRIDE + ldc] =
                make_uint4(f2tf(vregs[i].x), f2tf(vregs[i].y),
                           f2tf(vregs[i].z), f2tf(vregs[i].w));
        }
        if (kt + 1 < SEQ / 64) {
            const float* kb = Kbase + (size_t)(kt + 1) * 64 * D_MODEL;
#pragma unroll
            for (int i = 0; i < 4; i++)
                kregs[i] = *(const float4*)(kb + (size_t)(ldr + i * 16) * D_MODEL + ldc);
        }
        __syncthreads();

        // O += P @ V — overlaps next-K gmem load
#pragma unroll
        for (int kc = 0; kc < 8; kc++) {
            uint32_t pa[4];
            pa[0] = Ps[r0 * QS_STRIDE + kc * 8 + tig];
            pa[1] = Ps[(r0 + 8) * QS_STRIDE + kc * 8 + tig];
            pa[2] = Ps[r0 * QS_STRIDE + kc * 8 + tig + 4];
            pa[3] = Ps[(r0 + 8) * QS_STRIDE + kc * 8 + tig + 4];
#pragma unroll
            for (int nt = 0; nt < 8; nt++) {
                uint32_t vf[2];
                vf[0] = Vs[(kc * 8 + tig) * VS_STRIDE + nt * 8 + gid];
                vf[1] = Vs[(kc * 8 + tig + 4) * VS_STRIDE + nt * 8 + gid];
                mma_tf32(o[nt], pa, vf, o[nt]);
            }
        }
    }

    float inv0 = 1.0f / l0, inv1 = 1.0f / l1;
    float* obase = O + ((size_t)b * SEQ + qt * 128) * D_MODEL + h * DK;
#pragma unroll
    for (int nt = 0; nt < 8; nt++) {
        int col = nt * 8 + 2 * tig;
        *(float2*)(obase + (size_t)r0 * D_MODEL + col) =
            make_float2(o[nt][0] * inv0, o[nt][1] * inv0);
        *(float2*)(obase + (size_t)(r0 + 8) * D_MODEL + col) =
            make_float2(o[nt][2] * inv1, o[nt][3] * inv1);
    }
}

// ---------------------------------------------------------------------------
extern "C" void kernel_launch(void* const* d_in, const int* in_sizes, int n_in,
                              void* d_out, int out_size) {
    const float* x  = (const float*)d_in[0];
    const float* Wq = (const float*)d_in[1];
    const float* Wk = (const float*)d_in[2];
    const float* Wv = (const float*)d_in[3];
    const float* Wo = (const float*)d_in[4];
    float* out = (float*)d_out;

    float *Qp, *Kp, *Vp, *Ap;
    cudaGetSymbolAddress((void**)&Qp, g_Q);
    cudaGetSymbolAddress((void**)&Kp, g_K);
    cudaGetSymbolAddress((void**)&Vp, g_V);
    cudaGetSymbolAddress((void**)&Ap, g_att);

    dim3 qkv_grid(D_MODEL / 128, MTOT / 128, 3);
    gemm_qkv_kernel<<<qkv_grid, 256>>>(x, Wq, Wk, Wv);

    cudaFuncSetAttribute(attn_kernel, cudaFuncAttributeMaxDynamicSharedMemorySize,
                         ATTN_SMEM_BYTES);
    attn_kernel<<<dim3(SEQ / 128, NHEAD, BATCH), 256, ATTN_SMEM_BYTES>>>(Qp, Kp, Vp, Ap);

    dim3 o_grid(D_MODEL / 128, MTOT / 128);
    gemm_kernel<<<o_grid, 256>>>(Ap, Wo, out, MTOT, D_MODEL, D_MODEL);
}